// round 4
// baseline (speedup 1.0000x reference)
#include <cuda_runtime.h>
#include <cuda_bf16.h>
#include <cstdint>

#define N_NODES 100000
#define N_EDGES 1600000
#define D 128

typedef unsigned long long ull;

// ---------------- device scratch (no cudaMalloc allowed) ----------------
__device__ int   g_deg[N_NODES];
__device__ int   g_off[N_NODES + 1];
__device__ int   g_cur[N_NODES];
__device__ int   g_csr[N_EDGES];
__device__ int   g_tsum[4096];
__device__ int   g_is_i32;      // 1 if edge_index buffer is int32, 0 if int64
__device__ float g_agg[(size_t)N_NODES * D];
__device__ float g_h  [(size_t)N_NODES * D];

#define SCAN_CHUNK 32
#define SCAN_NT    3328          // ceil(100000/32) rounded to 13*256

// ---------------- packed f32x2 helpers (Blackwell FFMA2) ----------------
__device__ __forceinline__ ull fma2(ull a, ull b, ull c) {
    ull d;
    asm("fma.rn.f32x2 %0, %1, %2, %3;" : "=l"(d) : "l"(a), "l"(b), "l"(c));
    return d;
}
__device__ __forceinline__ ull pack2(float x, float y) {
    ull d;
    asm("mov.b64 %0, {%1, %2};" : "=l"(d) : "f"(x), "f"(y));
    return d;
}
__device__ __forceinline__ void unpack2(ull d, float& x, float& y) {
    asm("mov.b64 {%0, %1}, %2;" : "=f"(x), "=f"(y) : "l"(d));
}

// ---------------- dtype detection + CSR build ----------------
__global__ void zero_deg_kernel() {
    int i = blockIdx.x * blockDim.x + threadIdx.x;
    if (i < N_NODES) g_deg[i] = 0;
    if (i == 0) g_is_i32 = 0;
}

// Sample first 64K 64-bit slots (safe under either dtype: 512KB << 12.8MB).
// int64 data: every value < N_NODES. int32 data: slot packs two ids; value
// >= 2^32 whenever the high id > 0 (prob 1-1e-5 per slot).
__global__ void detect_dtype_kernel(const unsigned long long* __restrict__ ei) {
    int e = blockIdx.x * blockDim.x + threadIdx.x;
    if (e < 65536) {
        if (ei[e] >= (unsigned long long)N_NODES) atomicOr(&g_is_i32, 1);
    }
}

__device__ __forceinline__ void load_edge(const void* ei, int e, int is32,
                                          int& s, int& d) {
    if (is32) {
        const int* p = (const int*)ei;
        s = p[e];
        d = p[N_EDGES + e];
    } else {
        const long long* p = (const long long*)ei;
        s = (int)p[e];
        d = (int)p[N_EDGES + e];
    }
}

__global__ void hist_kernel(const void* __restrict__ ei) {
    int e = blockIdx.x * blockDim.x + threadIdx.x;
    if (e < N_EDGES) {
        int s, d;
        load_edge(ei, e, g_is_i32, s, d);
        if ((unsigned)d < (unsigned)N_NODES) atomicAdd(&g_deg[d], 1);
    }
}

// ---- multi-block exclusive scan of g_deg -> g_off/g_cur (3 tiny kernels) ----
__global__ void scanA_kernel() {   // per-thread chunk sums
    int t = blockIdx.x * blockDim.x + threadIdx.x;
    if (t >= SCAN_NT) return;
    int st = t * SCAN_CHUNK;
    int en = st + SCAN_CHUNK; if (en > N_NODES) en = N_NODES;
    int s = 0;
    for (int i = st; i < en && i < N_NODES; i++) s += g_deg[i];
    g_tsum[t] = s;
}

__global__ void scanB_kernel() {   // 1 block scans 3328 partials
    __shared__ int s[1024];
    int t = threadIdx.x;
    int v[4];
    int sum = 0;
#pragma unroll
    for (int q = 0; q < 4; q++) {
        int j = t * 4 + q;
        int xv = (j < SCAN_NT) ? g_tsum[j] : 0;
        v[q] = sum;           // local exclusive prefix
        sum += xv;
    }
    s[t] = sum;
    __syncthreads();
    for (int d = 1; d < 1024; d <<= 1) {
        int u = 0;
        if (t >= d) u = s[t - d];
        __syncthreads();
        s[t] += u;
        __syncthreads();
    }
    int base = (t > 0) ? s[t - 1] : 0;
#pragma unroll
    for (int q = 0; q < 4; q++) {
        int j = t * 4 + q;
        if (j < SCAN_NT) g_tsum[j] = base + v[q];
    }
    if (t == 1023) g_off[N_NODES] = s[1023];
}

__global__ void scanC_kernel() {   // per-thread offset writeback
    int t = blockIdx.x * blockDim.x + threadIdx.x;
    if (t >= SCAN_NT) return;
    int st = t * SCAN_CHUNK;
    int en = st + SCAN_CHUNK; if (en > N_NODES) en = N_NODES;
    int base = g_tsum[t];
    for (int i = st; i < en && i < N_NODES; i++) {
        g_off[i] = base;
        g_cur[i] = base;
        base += g_deg[i];
    }
}

__global__ void fill_kernel(const void* __restrict__ ei) {
    int e = blockIdx.x * blockDim.x + threadIdx.x;
    if (e < N_EDGES) {
        int s, d;
        load_edge(ei, e, g_is_i32, s, d);
        if ((unsigned)d < (unsigned)N_NODES && (unsigned)s < (unsigned)N_NODES) {
            int p = atomicAdd(&g_cur[d], 1);
            g_csr[p] = s;
        }
    }
}

// ---------------- aggregation: warp per node, mean of neighbor rows ----------
__global__ void agg_kernel(const float* __restrict__ x, int use_h) {
    int gw = (blockIdx.x * blockDim.x + threadIdx.x) >> 5;
    int lane = threadIdx.x & 31;
    if (gw >= N_NODES) return;
    const float* feat = use_h ? (const float*)g_h : x;
    int b = g_off[gw];
    int e = g_off[gw + 1];
    float4 acc = make_float4(0.f, 0.f, 0.f, 0.f);
    for (int j = b; j < e; j++) {
        int sN = g_csr[j];
        float4 v = *(const float4*)(feat + (size_t)sN * D + lane * 4);
        acc.x += v.x; acc.y += v.y; acc.z += v.z; acc.w += v.w;
    }
    int cnt = e - b;
    float inv = 1.0f / (float)(cnt > 0 ? cnt : 1);
    acc.x *= inv; acc.y *= inv; acc.z *= inv; acc.w *= inv;
    *(float4*)(g_agg + (size_t)gw * D + lane * 4) = acc;
}

// ---------------- fused dual GEMM with packed f32x2 (FFMA2) ------------------
// out = g_agg@Wl + self@Wr + bias (opt. relu)
// 128 nodes x 128 cols per block, 256 threads, 8 nodes x 8 cols per thread.
// Accumulators packed over node-pairs: acc[ii][j] = (out[2ii], out[2ii+1]) x col j.
// A tile stored transposed sAT[k][node] so node-pairs load as 64-bit lanes.
#define APAD 132   // row stride (floats) for sAT: 16B-aligned rows, 4-way store conflict only
__global__ __launch_bounds__(256, 2) void gemm_kernel(
    const float* __restrict__ x,
    const float* __restrict__ Wl,
    const float* __restrict__ Wr,
    const float* __restrict__ bias,
    float* __restrict__ out,
    int self_from_h, int out_to_h, int do_relu)
{
    __shared__ float sAT[32 * APAD];   // [k][node] transposed
    __shared__ float sW[32][128];      // [k][col]

    int tid = threadIdx.x;
    int r = tid >> 4;    // 0..15 node group (rows r*8 .. r*8+7)
    int c = tid & 15;    // 0..15 col group (cols c*8 .. c*8+7)
    int node0 = blockIdx.x * 128;

    const float* A1 = self_from_h ? (const float*)g_h : x;
    float* dst = out_to_h ? (float*)g_h : out;

    ull acc[4][8];
#pragma unroll
    for (int i = 0; i < 4; i++)
#pragma unroll
        for (int j = 0; j < 8; j++) acc[i][j] = 0ULL;

    for (int kc = 0; kc < 256; kc += 32) {
        const float* Wsrc = (kc < 128) ? (Wl + kc * D) : (Wr + (kc - 128) * D);
        const float* Asrc = (kc < 128) ? (const float*)g_agg : A1;
        int kbase = (kc < 128) ? kc : (kc - 128);

        // load W chunk 32x128 (coalesced float4)
#pragma unroll
        for (int i = 0; i < 4; i++) {
            int idx = tid + i * 256;
            int kk = idx >> 5;
            int c4 = idx & 31;
            float4 v = *(const float4*)(Wsrc + kk * D + c4 * 4);
            *(float4*)(&sW[kk][c4 * 4]) = v;
        }
        // load A chunk 128 nodes x 32 k, transpose into sAT[k][node]
#pragma unroll
        for (int i = 0; i < 4; i++) {
            int idx = tid + i * 256;
            int n = idx >> 3;            // 0..127
            int k4 = idx & 7;            // 0..7
            int node = node0 + n;
            float4 v = make_float4(0.f, 0.f, 0.f, 0.f);
            if (node < N_NODES)
                v = *(const float4*)(Asrc + (size_t)node * D + kbase + k4 * 4);
            float* col = &sAT[(k4 * 4) * APAD + n];
            col[0 * APAD] = v.x;
            col[1 * APAD] = v.y;
            col[2 * APAD] = v.z;
            col[3 * APAD] = v.w;
        }
        __syncthreads();

#pragma unroll 8
        for (int k = 0; k < 32; k++) {
            // A node-pairs: two LDS.128, each 64-bit lane = packed (even,odd)
            const ulonglong2* pa = (const ulonglong2*)&sAT[k * APAD + r * 8];
            ulonglong2 aA = pa[0];      // nodes r*8+0..3
            ulonglong2 aB = pa[1];      // nodes r*8+4..7
            ull a2[4] = {aA.x, aA.y, aB.x, aB.y};
            // W cols, duplicated into pairs
            float4 wlo = *(const float4*)&sW[k][c * 8];
            float4 whi = *(const float4*)&sW[k][c * 8 + 4];
            ull w2[8];
            w2[0] = pack2(wlo.x, wlo.x); w2[1] = pack2(wlo.y, wlo.y);
            w2[2] = pack2(wlo.z, wlo.z); w2[3] = pack2(wlo.w, wlo.w);
            w2[4] = pack2(whi.x, whi.x); w2[5] = pack2(whi.y, whi.y);
            w2[6] = pack2(whi.z, whi.z); w2[7] = pack2(whi.w, whi.w);
#pragma unroll
            for (int ii = 0; ii < 4; ii++)
#pragma unroll
                for (int j = 0; j < 8; j++)
                    acc[ii][j] = fma2(a2[ii], w2[j], acc[ii][j]);
        }
        __syncthreads();
    }

    // epilogue: bias + relu + vectorized store
    float4 b03 = *(const float4*)&bias[c * 8];
    float4 b47 = *(const float4*)&bias[c * 8 + 4];
    float bj[8] = {b03.x, b03.y, b03.z, b03.w, b47.x, b47.y, b47.z, b47.w};

#pragma unroll
    for (int ii = 0; ii < 4; ii++) {
        int nodeE = node0 + r * 8 + ii * 2;
        float lo[8], hi[8];
#pragma unroll
        for (int j = 0; j < 8; j++) {
            unpack2(acc[ii][j], lo[j], hi[j]);
            lo[j] += bj[j];
            hi[j] += bj[j];
            if (do_relu) {
                lo[j] = fmaxf(lo[j], 0.f);
                hi[j] = fmaxf(hi[j], 0.f);
            }
        }
        if (nodeE < N_NODES) {
            float* p = dst + (size_t)nodeE * D + c * 8;
            *(float4*)(p)     = make_float4(lo[0], lo[1], lo[2], lo[3]);
            *(float4*)(p + 4) = make_float4(lo[4], lo[5], lo[6], lo[7]);
        }
        if (nodeE + 1 < N_NODES) {
            float* p = dst + (size_t)(nodeE + 1) * D + c * 8;
            *(float4*)(p)     = make_float4(hi[0], hi[1], hi[2], hi[3]);
            *(float4*)(p + 4) = make_float4(hi[4], hi[5], hi[6], hi[7]);
        }
    }
}

// ---------------- launch ----------------
extern "C" void kernel_launch(void* const* d_in, const int* in_sizes, int n_in,
                              void* d_out, int out_size) {
    const float* x   = (const float*)d_in[0];
    const void*  ei  = d_in[1];
    const float* Wl1 = (const float*)d_in[2];
    const float* b1  = (const float*)d_in[3];
    const float* Wr1 = (const float*)d_in[4];
    const float* Wl2 = (const float*)d_in[5];
    const float* b2  = (const float*)d_in[6];
    const float* Wr2 = (const float*)d_in[7];
    float* out = (float*)d_out;

    zero_deg_kernel<<<(N_NODES + 255) / 256, 256>>>();
    detect_dtype_kernel<<<256, 256>>>((const unsigned long long*)ei);
    hist_kernel<<<(N_EDGES + 255) / 256, 256>>>(ei);
    scanA_kernel<<<SCAN_NT / 256, 256>>>();
    scanB_kernel<<<1, 1024>>>();
    scanC_kernel<<<SCAN_NT / 256, 256>>>();
    fill_kernel<<<(N_EDGES + 255) / 256, 256>>>(ei);

    // layer 1: agg(x) -> g_agg ; g_h = relu(g_agg@Wl1 + b1 + x@Wr1)
    agg_kernel<<<(N_NODES * 32 + 255) / 256, 256>>>(x, 0);
    gemm_kernel<<<(N_NODES + 127) / 128, 256>>>(x, Wl1, Wr1, b1, out, 0, 1, 1);

    // layer 2: agg(g_h) -> g_agg ; out = g_agg@Wl2 + b2 + g_h@Wr2
    agg_kernel<<<(N_NODES * 32 + 255) / 256, 256>>>(x, 1);
    gemm_kernel<<<(N_NODES + 127) / 128, 256>>>(x, Wl2, Wr2, b2, out, 1, 0, 0);
}

// round 5
// speedup vs baseline: 1.3115x; 1.3115x over previous
#include <cuda_runtime.h>
#include <cuda_bf16.h>
#include <cstdint>

#define N_NODES 100000
#define N_EDGES 1600000
#define D 128

// ---------------- device scratch (no cudaMalloc allowed) ----------------
__device__ int   g_deg[N_NODES];
__device__ int   g_off[N_NODES + 1];
__device__ int   g_cur[N_NODES];
__device__ int   g_csr[N_EDGES];
__device__ int   g_tsum[4096];
__device__ int   g_is_i32;      // 1 if edge_index buffer is int32, 0 if int64
__device__ float g_agg[(size_t)N_NODES * D];
__device__ float g_h  [(size_t)N_NODES * D];

#define SCAN_CHUNK 32
#define SCAN_NT    3328          // ceil(100000/32) rounded to 13*256

// ---------------- dtype detection + CSR build ----------------
__global__ void zero_deg_kernel() {
    int i = blockIdx.x * blockDim.x + threadIdx.x;
    if (i < N_NODES) g_deg[i] = 0;
    if (i == 0) g_is_i32 = 0;
}

// Sample first 64K 64-bit slots (512KB << 12.8MB buffer, safe either dtype).
// int64 data: every value is a node id < N_NODES. int32 data: slot packs two
// ids; value >= 2^32 whenever the high id > 0 (prob 1-1e-5 per slot).
__global__ void detect_dtype_kernel(const unsigned long long* __restrict__ ei) {
    int e = blockIdx.x * blockDim.x + threadIdx.x;
    if (e < 65536) {
        if (ei[e] >= (unsigned long long)N_NODES) atomicOr(&g_is_i32, 1);
    }
}

__device__ __forceinline__ void load_edge(const void* ei, int e, int is32,
                                          int& s, int& d) {
    if (is32) {
        const int* p = (const int*)ei;
        s = p[e];
        d = p[N_EDGES + e];
    } else {
        const long long* p = (const long long*)ei;
        s = (int)p[e];
        d = (int)p[N_EDGES + e];
    }
}

__global__ void hist_kernel(const void* __restrict__ ei) {
    int e = blockIdx.x * blockDim.x + threadIdx.x;
    if (e < N_EDGES) {
        int s, d;
        load_edge(ei, e, g_is_i32, s, d);
        if ((unsigned)d < (unsigned)N_NODES) atomicAdd(&g_deg[d], 1);
    }
}

// ---- multi-block exclusive scan of g_deg -> g_off/g_cur (3 tiny kernels) ----
__global__ void scanA_kernel() {   // per-thread chunk sums
    int t = blockIdx.x * blockDim.x + threadIdx.x;
    if (t >= SCAN_NT) return;
    int st = t * SCAN_CHUNK;
    int en = st + SCAN_CHUNK; if (en > N_NODES) en = N_NODES;
    int s = 0;
    for (int i = st; i < en; i++) s += g_deg[i];
    g_tsum[t] = s;
}

__global__ void scanB_kernel() {   // 1 block scans 3328 partials
    __shared__ int s[1024];
    int t = threadIdx.x;
    int v[4];
    int sum = 0;
#pragma unroll
    for (int q = 0; q < 4; q++) {
        int j = t * 4 + q;
        int xv = (j < SCAN_NT) ? g_tsum[j] : 0;
        v[q] = sum;           // local exclusive prefix
        sum += xv;
    }
    s[t] = sum;
    __syncthreads();
    for (int d = 1; d < 1024; d <<= 1) {
        int u = 0;
        if (t >= d) u = s[t - d];
        __syncthreads();
        s[t] += u;
        __syncthreads();
    }
    int base = (t > 0) ? s[t - 1] : 0;
#pragma unroll
    for (int q = 0; q < 4; q++) {
        int j = t * 4 + q;
        if (j < SCAN_NT) g_tsum[j] = base + v[q];
    }
    if (t == 1023) g_off[N_NODES] = s[1023];
}

__global__ void scanC_kernel() {   // per-thread offset writeback
    int t = blockIdx.x * blockDim.x + threadIdx.x;
    if (t >= SCAN_NT) return;
    int st = t * SCAN_CHUNK;
    int en = st + SCAN_CHUNK; if (en > N_NODES) en = N_NODES;
    int base = g_tsum[t];
    for (int i = st; i < en; i++) {
        g_off[i] = base;
        g_cur[i] = base;
        base += g_deg[i];
    }
}

__global__ void fill_kernel(const void* __restrict__ ei) {
    int e = blockIdx.x * blockDim.x + threadIdx.x;
    if (e < N_EDGES) {
        int s, d;
        load_edge(ei, e, g_is_i32, s, d);
        if ((unsigned)d < (unsigned)N_NODES && (unsigned)s < (unsigned)N_NODES) {
            int p = atomicAdd(&g_cur[d], 1);
            g_csr[p] = s;
        }
    }
}

// ---------------- aggregation: warp per node, mean of neighbor rows ----------
__global__ void agg_kernel(const float* __restrict__ x, int use_h) {
    int gw = (blockIdx.x * blockDim.x + threadIdx.x) >> 5;
    int lane = threadIdx.x & 31;
    if (gw >= N_NODES) return;
    const float* feat = use_h ? (const float*)g_h : x;
    int b = g_off[gw];
    int e = g_off[gw + 1];
    float4 acc = make_float4(0.f, 0.f, 0.f, 0.f);
    for (int j = b; j < e; j++) {
        int sN = g_csr[j];
        float4 v = *(const float4*)(feat + (size_t)sN * D + lane * 4);
        acc.x += v.x; acc.y += v.y; acc.z += v.z; acc.w += v.w;
    }
    int cnt = e - b;
    float inv = 1.0f / (float)(cnt > 0 ? cnt : 1);
    acc.x *= inv; acc.y *= inv; acc.z *= inv; acc.w *= inv;
    *(float4*)(g_agg + (size_t)gw * D + lane * 4) = acc;
}

// ---------------- fused dual GEMM: out = g_agg@Wl + self@Wr + b (opt. relu) --
// 128 nodes x 128 cols per block, 256 threads, 8x8 per thread. (round-3 proven)
__global__ __launch_bounds__(256, 2) void gemm_kernel(
    const float* __restrict__ x,
    const float* __restrict__ Wl,
    const float* __restrict__ Wr,
    const float* __restrict__ bias,
    float* __restrict__ out,
    int self_from_h, int out_to_h, int do_relu)
{
    __shared__ float sA[128][36];
    __shared__ float sW[32][128];

    int tid = threadIdx.x;
    int r = tid >> 4;
    int c = tid & 15;
    int node0 = blockIdx.x * 128;

    const float* A1 = self_from_h ? (const float*)g_h : x;
    float* dst = out_to_h ? (float*)g_h : out;

    float acc[8][8];
#pragma unroll
    for (int i = 0; i < 8; i++)
#pragma unroll
        for (int j = 0; j < 8; j++) acc[i][j] = 0.f;

    for (int kc = 0; kc < 256; kc += 32) {
        const float* Wsrc = (kc < 128) ? (Wl + kc * D) : (Wr + (kc - 128) * D);
        const float* Asrc = (kc < 128) ? (const float*)g_agg : A1;
        int kbase = (kc < 128) ? kc : (kc - 128);

#pragma unroll
        for (int i = 0; i < 4; i++) {
            int idx = tid + i * 256;
            int kk = idx >> 5;
            int c4 = idx & 31;
            float4 v = *(const float4*)(Wsrc + kk * D + c4 * 4);
            *(float4*)(&sW[kk][c4 * 4]) = v;
        }
#pragma unroll
        for (int i = 0; i < 4; i++) {
            int idx = tid + i * 256;
            int n = idx >> 3;
            int k4 = idx & 7;
            int node = node0 + n;
            float4 v = make_float4(0.f, 0.f, 0.f, 0.f);
            if (node < N_NODES)
                v = *(const float4*)(Asrc + (size_t)node * D + kbase + k4 * 4);
            *(float4*)(&sA[n][k4 * 4]) = v;
        }
        __syncthreads();

#pragma unroll 8
        for (int k = 0; k < 32; k++) {
            float wv[8];
#pragma unroll
            for (int j = 0; j < 8; j++) wv[j] = sW[k][c * 8 + j];
            float av[8];
#pragma unroll
            for (int i = 0; i < 8; i++) av[i] = sA[r * 8 + i][k];
#pragma unroll
            for (int i = 0; i < 8; i++)
#pragma unroll
                for (int j = 0; j < 8; j++)
                    acc[i][j] = fmaf(av[i], wv[j], acc[i][j]);
        }
        __syncthreads();
    }

#pragma unroll
    for (int i = 0; i < 8; i++) {
        int node = node0 + r * 8 + i;
        if (node >= N_NODES) continue;
#pragma unroll
        for (int j = 0; j < 8; j++) {
            int col = c * 8 + j;
            float v = acc[i][j] + bias[col];
            if (do_relu) v = fmaxf(v, 0.f);
            dst[(size_t)node * D + col] = v;
        }
    }
}

// ---------------- launch ----------------
extern "C" void kernel_launch(void* const* d_in, const int* in_sizes, int n_in,
                              void* d_out, int out_size) {
    const float* x   = (const float*)d_in[0];
    const void*  ei  = d_in[1];
    const float* Wl1 = (const float*)d_in[2];
    const float* b1  = (const float*)d_in[3];
    const float* Wr1 = (const float*)d_in[4];
    const float* Wl2 = (const float*)d_in[5];
    const float* b2  = (const float*)d_in[6];
    const float* Wr2 = (const float*)d_in[7];
    float* out = (float*)d_out;

    zero_deg_kernel<<<(N_NODES + 255) / 256, 256>>>();
    detect_dtype_kernel<<<256, 256>>>((const unsigned long long*)ei);
    hist_kernel<<<(N_EDGES + 255) / 256, 256>>>(ei);
    scanA_kernel<<<SCAN_NT / 256, 256>>>();
    scanB_kernel<<<1, 1024>>>();
    scanC_kernel<<<SCAN_NT / 256, 256>>>();
    fill_kernel<<<(N_EDGES + 255) / 256, 256>>>(ei);

    // layer 1: agg(x) -> g_agg ; g_h = relu(g_agg@Wl1 + b1 + x@Wr1)
    agg_kernel<<<(N_NODES * 32 + 255) / 256, 256>>>(x, 0);
    gemm_kernel<<<(N_NODES + 127) / 128, 256>>>(x, Wl1, Wr1, b1, out, 0, 1, 1);

    // layer 2: agg(g_h) -> g_agg ; out = g_agg@Wl2 + b2 + g_h@Wr2
    agg_kernel<<<(N_NODES * 32 + 255) / 256, 256>>>(x, 1);
    gemm_kernel<<<(N_NODES + 127) / 128, 256>>>(x, Wl2, Wr2, b2, out, 1, 0, 0);
}

// round 7
// speedup vs baseline: 1.9827x; 1.5118x over previous
#include <cuda_runtime.h>
#include <cuda_bf16.h>
#include <cstdint>

#define N_NODES 100000
#define N_EDGES 1600000
#define D 128

// ---------------- device scratch (no cudaMalloc allowed) ----------------
__device__ int   g_deg[N_NODES];
__device__ int   g_off[N_NODES + 1];
__device__ int   g_cur[N_NODES];
__device__ int   g_csr[N_EDGES];
__device__ int   g_tsum[4096];
__device__ int   g_is_i32;
__device__ float g_agg[(size_t)N_NODES * D];
__device__ float g_h  [(size_t)N_NODES * D];
// pre-split weights: [layer][pass][col c][k] bf16 (B = W^T, K-major)
__device__ __nv_bfloat16 g_Bh[2][2][128][128];
__device__ __nv_bfloat16 g_Bl[2][2][128][128];

#define SCAN_CHUNK 32
#define SCAN_NT    3328

// ---------------- dtype detection + CSR build (round-5 proven) ----------
__global__ void zero_deg_kernel() {
    int i = blockIdx.x * blockDim.x + threadIdx.x;
    if (i < N_NODES) g_deg[i] = 0;
    if (i == 0) g_is_i32 = 0;
}

__global__ void detect_dtype_kernel(const unsigned long long* __restrict__ ei) {
    int e = blockIdx.x * blockDim.x + threadIdx.x;
    if (e < 65536) {
        if (ei[e] >= (unsigned long long)N_NODES) atomicOr(&g_is_i32, 1);
    }
}

__device__ __forceinline__ void load_edge(const void* ei, int e, int is32,
                                          int& s, int& d) {
    if (is32) {
        const int* p = (const int*)ei;
        s = p[e];
        d = p[N_EDGES + e];
    } else {
        const long long* p = (const long long*)ei;
        s = (int)p[e];
        d = (int)p[N_EDGES + e];
    }
}

__global__ void hist_kernel(const void* __restrict__ ei) {
    int e = blockIdx.x * blockDim.x + threadIdx.x;
    if (e < N_EDGES) {
        int s, d;
        load_edge(ei, e, g_is_i32, s, d);
        if ((unsigned)d < (unsigned)N_NODES) atomicAdd(&g_deg[d], 1);
    }
}

__global__ void scanA_kernel() {
    int t = blockIdx.x * blockDim.x + threadIdx.x;
    if (t >= SCAN_NT) return;
    int st = t * SCAN_CHUNK;
    int en = st + SCAN_CHUNK; if (en > N_NODES) en = N_NODES;
    int s = 0;
    for (int i = st; i < en; i++) s += g_deg[i];
    g_tsum[t] = s;
}

__global__ void scanB_kernel() {
    __shared__ int s[1024];
    int t = threadIdx.x;
    int v[4];
    int sum = 0;
#pragma unroll
    for (int q = 0; q < 4; q++) {
        int j = t * 4 + q;
        int xv = (j < SCAN_NT) ? g_tsum[j] : 0;
        v[q] = sum;
        sum += xv;
    }
    s[t] = sum;
    __syncthreads();
    for (int d = 1; d < 1024; d <<= 1) {
        int u = 0;
        if (t >= d) u = s[t - d];
        __syncthreads();
        s[t] += u;
        __syncthreads();
    }
    int base = (t > 0) ? s[t - 1] : 0;
#pragma unroll
    for (int q = 0; q < 4; q++) {
        int j = t * 4 + q;
        if (j < SCAN_NT) g_tsum[j] = base + v[q];
    }
    if (t == 1023) g_off[N_NODES] = s[1023];
}

__global__ void scanC_kernel() {
    int t = blockIdx.x * blockDim.x + threadIdx.x;
    if (t >= SCAN_NT) return;
    int st = t * SCAN_CHUNK;
    int en = st + SCAN_CHUNK; if (en > N_NODES) en = N_NODES;
    int base = g_tsum[t];
    for (int i = st; i < en; i++) {
        g_off[i] = base;
        g_cur[i] = base;
        base += g_deg[i];
    }
}

__global__ void fill_kernel(const void* __restrict__ ei) {
    int e = blockIdx.x * blockDim.x + threadIdx.x;
    if (e < N_EDGES) {
        int s, d;
        load_edge(ei, e, g_is_i32, s, d);
        if ((unsigned)d < (unsigned)N_NODES && (unsigned)s < (unsigned)N_NODES) {
            int p = atomicAdd(&g_cur[d], 1);
            g_csr[p] = s;
        }
    }
}

// ---------------- aggregation (round-5 proven) ---------------------------
__global__ void agg_kernel(const float* __restrict__ x, int use_h) {
    int gw = (blockIdx.x * blockDim.x + threadIdx.x) >> 5;
    int lane = threadIdx.x & 31;
    if (gw >= N_NODES) return;
    const float* feat = use_h ? (const float*)g_h : x;
    int b = g_off[gw];
    int e = g_off[gw + 1];
    float4 acc = make_float4(0.f, 0.f, 0.f, 0.f);
    for (int j = b; j < e; j++) {
        int sN = g_csr[j];
        float4 v = *(const float4*)(feat + (size_t)sN * D + lane * 4);
        acc.x += v.x; acc.y += v.y; acc.z += v.z; acc.w += v.w;
    }
    int cnt = e - b;
    float inv = 1.0f / (float)(cnt > 0 ? cnt : 1);
    acc.x *= inv; acc.y *= inv; acc.z *= inv; acc.w *= inv;
    *(float4*)(g_agg + (size_t)gw * D + lane * 4) = acc;
}

// ---------------- weight prep: transpose + bf16 hi/lo split --------------
__global__ void prep_w_kernel(const float* __restrict__ Wl1,
                              const float* __restrict__ Wr1,
                              const float* __restrict__ Wl2,
                              const float* __restrict__ Wr2) {
    int i = blockIdx.x * blockDim.x + threadIdx.x;   // 65536
    if (i >= 2 * 2 * 128 * 128) return;
    int layer = i >> 15;
    int pass  = (i >> 14) & 1;
    int c     = (i >> 7) & 127;
    int k     = i & 127;
    const float* W = (layer == 0) ? (pass == 0 ? Wl1 : Wr1)
                                  : (pass == 0 ? Wl2 : Wr2);
    float v = W[k * 128 + c];                        // B[c][k] = W[k][c]
    __nv_bfloat16 h = __float2bfloat16(v);
    __nv_bfloat16 l = __float2bfloat16(v - __bfloat162float(h));
    g_Bh[layer][pass][c][k] = h;
    g_Bl[layer][pass][c][k] = l;
}

// ---------------- mma.sync bf16 3-chain split GEMM -----------------------
// D[128 nodes][128 cols] per block. 8 warps: warp_m in 0..3 (32 rows),
// warp_n in 0..1 (64 cols). K processed in 4 chunks of 32.
// fp32 accumulate; chains Ah*Bh + Ah*Bl + Al*Bh.
#define KPAD 40   // smem row stride in bf16 (80B): conflict-free frag loads

__device__ __forceinline__ void mma16816(float* c, const uint32_t* a,
                                         uint32_t b0, uint32_t b1) {
    asm volatile(
        "mma.sync.aligned.m16n8k16.row.col.f32.bf16.bf16.f32 "
        "{%0,%1,%2,%3}, {%4,%5,%6,%7}, {%8,%9}, {%0,%1,%2,%3};"
        : "+f"(c[0]), "+f"(c[1]), "+f"(c[2]), "+f"(c[3])
        : "r"(a[0]), "r"(a[1]), "r"(a[2]), "r"(a[3]), "r"(b0), "r"(b1));
}
__device__ __forceinline__ uint32_t pk2(float a, float b) {
    __nv_bfloat162 t = __floats2bfloat162_rn(a, b);
    return *reinterpret_cast<uint32_t*>(&t);
}

__global__ void __launch_bounds__(256) mma_gemm_kernel(
    const float* __restrict__ x,
    const float* __restrict__ bias,
    float* __restrict__ out,
    int layer, int self_from_h, int out_to_h, int do_relu)
{
    __shared__ __nv_bfloat16 sAh[128][KPAD];
    __shared__ __nv_bfloat16 sAl[128][KPAD];
    __shared__ __nv_bfloat16 sBh[128][KPAD];
    __shared__ __nv_bfloat16 sBl[128][KPAD];

    int tid = threadIdx.x;
    int warp = tid >> 5;
    int lane = tid & 31;
    int warp_m = warp >> 1;          // 0..3
    int warp_n = warp & 1;           // 0..1
    int g = lane >> 2;               // 0..7
    int q = (lane & 3) * 2;          // 0,2,4,6
    int node0 = blockIdx.x * 128;

    const float* A1 = self_from_h ? (const float*)g_h : x;
    float* dst = out_to_h ? (float*)g_h : out;

    float C[2][8][4];
#pragma unroll
    for (int mt = 0; mt < 2; mt++)
#pragma unroll
        for (int nt = 0; nt < 8; nt++)
#pragma unroll
            for (int e = 0; e < 4; e++) C[mt][nt][e] = 0.f;

    for (int pass = 0; pass < 2; pass++) {
        const float* Asrc = (pass == 0) ? (const float*)g_agg : A1;
        const __nv_bfloat16* Bh = &g_Bh[layer][pass][0][0];
        const __nv_bfloat16* Bl = &g_Bl[layer][pass][0][0];

        for (int kc = 0; kc < 4; kc++) {
            int k0 = kc * 32;
            // ---- A chunk: 128 nodes x 32 k fp32 -> split -> smem
#pragma unroll
            for (int it = 0; it < 4; it++) {
                int idx = tid + it * 256;     // 0..1023 float4 slots
                int n  = idx >> 3;            // node row 0..127
                int kq = (idx & 7) * 4;       // 0..28
                int node = node0 + n;
                float4 v = make_float4(0.f, 0.f, 0.f, 0.f);
                if (node < N_NODES)
                    v = *(const float4*)(Asrc + (size_t)node * D + k0 + kq);
                float hx = __bfloat162float(__float2bfloat16(v.x));
                float hy = __bfloat162float(__float2bfloat16(v.y));
                float hz = __bfloat162float(__float2bfloat16(v.z));
                float hw = __bfloat162float(__float2bfloat16(v.w));
                uint2 uh = make_uint2(pk2(hx, hy), pk2(hz, hw));
                uint2 ul = make_uint2(pk2(v.x - hx, v.y - hy),
                                      pk2(v.z - hz, v.w - hw));
                *(uint2*)(&sAh[n][kq]) = uh;
                *(uint2*)(&sAl[n][kq]) = ul;
            }
            // ---- B chunk: 128 cols x 32 k bf16 from pre-split weights
#pragma unroll
            for (int it = 0; it < 4; it++) {
                int idx = tid + it * 256;
                int c  = idx >> 3;
                int kq = (idx & 7) * 4;
                *(uint2*)(&sBh[c][kq]) = *(const uint2*)(Bh + c * 128 + k0 + kq);
                *(uint2*)(&sBl[c][kq]) = *(const uint2*)(Bl + c * 128 + k0 + kq);
            }
            __syncthreads();

            // ---- compute 2 k-steps of 16
#pragma unroll
            for (int ks = 0; ks < 2; ks++) {
                int kb = ks * 16;
                uint32_t ah[2][4], al[2][4];
#pragma unroll
                for (int mt = 0; mt < 2; mt++) {
                    int r0 = warp_m * 32 + mt * 16 + g;
                    ah[mt][0] = *(const uint32_t*)&sAh[r0][kb + q];
                    ah[mt][1] = *(const uint32_t*)&sAh[r0 + 8][kb + q];
                    ah[mt][2] = *(const uint32_t*)&sAh[r0][kb + q + 8];
                    ah[mt][3] = *(const uint32_t*)&sAh[r0 + 8][kb + q + 8];
                    al[mt][0] = *(const uint32_t*)&sAl[r0][kb + q];
                    al[mt][1] = *(const uint32_t*)&sAl[r0 + 8][kb + q];
                    al[mt][2] = *(const uint32_t*)&sAl[r0][kb + q + 8];
                    al[mt][3] = *(const uint32_t*)&sAl[r0 + 8][kb + q + 8];
                }
#pragma unroll
                for (int nt = 0; nt < 8; nt++) {
                    int cb = warp_n * 64 + nt * 8 + g;
                    uint32_t bh0 = *(const uint32_t*)&sBh[cb][kb + q];
                    uint32_t bh1 = *(const uint32_t*)&sBh[cb][kb + q + 8];
                    uint32_t bl0 = *(const uint32_t*)&sBl[cb][kb + q];
                    uint32_t bl1 = *(const uint32_t*)&sBl[cb][kb + q + 8];
                    mma16816(C[0][nt], ah[0], bh0, bh1);
                    mma16816(C[1][nt], ah[1], bh0, bh1);
                    mma16816(C[0][nt], ah[0], bl0, bl1);
                    mma16816(C[1][nt], ah[1], bl0, bl1);
                    mma16816(C[0][nt], al[0], bh0, bh1);
                    mma16816(C[1][nt], al[1], bh0, bh1);
                }
            }
            __syncthreads();
        }
    }

    // ---- epilogue: bias + relu + float2 stores from fragments
#pragma unroll
    for (int nt = 0; nt < 8; nt++) {
        int col = warp_n * 64 + nt * 8 + q;
        float2 bv = *(const float2*)(bias + col);
#pragma unroll
        for (int mt = 0; mt < 2; mt++) {
            int r0 = node0 + warp_m * 32 + mt * 16 + g;
            float v0 = C[mt][nt][0] + bv.x;
            float v1 = C[mt][nt][1] + bv.y;
            float v2 = C[mt][nt][2] + bv.x;
            float v3 = C[mt][nt][3] + bv.y;
            if (do_relu) {
                v0 = fmaxf(v0, 0.f); v1 = fmaxf(v1, 0.f);
                v2 = fmaxf(v2, 0.f); v3 = fmaxf(v3, 0.f);
            }
            if (r0 < N_NODES)
                *(float2*)(dst + (size_t)r0 * D + col) = make_float2(v0, v1);
            if (r0 + 8 < N_NODES)
                *(float2*)(dst + (size_t)(r0 + 8) * D + col) = make_float2(v2, v3);
        }
    }
}

// ---------------- launch ----------------
extern "C" void kernel_launch(void* const* d_in, const int* in_sizes, int n_in,
                              void* d_out, int out_size) {
    const float* x   = (const float*)d_in[0];
    const void*  ei  = d_in[1];
    const float* Wl1 = (const float*)d_in[2];
    const float* b1  = (const float*)d_in[3];
    const float* Wr1 = (const float*)d_in[4];
    const float* Wl2 = (const float*)d_in[5];
    const float* b2  = (const float*)d_in[6];
    const float* Wr2 = (const float*)d_in[7];
    float* out = (float*)d_out;

    zero_deg_kernel<<<(N_NODES + 255) / 256, 256>>>();
    detect_dtype_kernel<<<256, 256>>>((const unsigned long long*)ei);
    hist_kernel<<<(N_EDGES + 255) / 256, 256>>>(ei);
    scanA_kernel<<<SCAN_NT / 256, 256>>>();
    scanB_kernel<<<1, 1024>>>();
    scanC_kernel<<<SCAN_NT / 256, 256>>>();
    fill_kernel<<<(N_EDGES + 255) / 256, 256>>>(ei);
    prep_w_kernel<<<256, 256>>>(Wl1, Wr1, Wl2, Wr2);

    int gblk = (N_NODES + 127) / 128;   // 782

    // layer 1: agg(x) -> g_agg ; g_h = relu(g_agg@Wl1 + b1 + x@Wr1)
    agg_kernel<<<(N_NODES * 32 + 255) / 256, 256>>>(x, 0);
    mma_gemm_kernel<<<gblk, 256>>>(x, b1, out, 0, 0, 1, 1);

    // layer 2: agg(g_h) -> g_agg ; out = g_agg@Wl2 + b2 + g_h@Wr2
    agg_kernel<<<(N_NODES * 32 + 255) / 256, 256>>>(x, 1);
    mma_gemm_kernel<<<gblk, 256>>>(x, b2, out, 1, 1, 0, 0);
}